// round 13
// baseline (speedup 1.0000x reference)
#include <cuda_runtime.h>
#include <cuda_bf16.h>
#include <cstdint>

// Problem constants
#define BATCH 4
#define NPTS  16384
#define KNN   16
#define CIN   64
#define DREL  64
#define CMID  128
#define COUT  128
#define LOG2E 1.4426950408889634f
#define NTHREADS 512

#define TP    4                        // points per team-group
#define G4    ((BATCH * NPTS) / TP)    // 16384 team-groups

// ---------------------------------------------------------------------------
// SMEM layout (bytes)
//   F (per team): [128 c rows][64 pk cols] bf16 hi/lo, row stride 144B
//                 (9x16B odd stride => conflict-free STS.128 + ldmatrix)
//   Wg hi/lo    : [128 o rows][128 c] bf16, row stride 272B (shared)
//   Wrel fp32, brel, bglob
//   Agg (per team): [16 rows (4 pts used)][128 c] bf16 hi/lo, stride 272B
// ---------------------------------------------------------------------------
#define FSTRIDE    144
#define F_TILE_T   (128 * FSTRIDE)        // 18432
#define TEAM_F     (2 * F_TILE_T)         // 36864 (hi + lo)
#define WG_STRIDE2 272
#define WG_TILE    (128 * WG_STRIDE2 + 64)  // 34880
#define OFF_WGH    (2 * TEAM_F)           // 73728
#define OFF_WGL    (OFF_WGH + WG_TILE)    // 108608
#define OFF_WREL   (OFF_WGL + WG_TILE)    // 143488
#define OFF_BREL   (OFF_WREL + 2560)
#define OFF_BGLOB  (OFF_BREL + 256)
#define OFF_AGG    (OFF_BGLOB + 512)      // 146816
#define AGG_TILE2  (16 * WG_STRIDE2)      // 4352
#define AGG_TEAM   (2 * AGG_TILE2)        // 8704
#define SMEM_BYTES (OFF_AGG + 2 * AGG_TEAM)   // 164224

// Scratch: packed bf16 hi/lo of transposed features: word = hi | (lo<<16)
__device__ uint32_t g_xtp[BATCH * NPTS * CIN];

// ---------------------------------------------------------------------------
static __device__ __forceinline__ uint32_t smem_u32(const void* p) {
    uint32_t a;
    asm("{ .reg .u64 t; cvta.to.shared.u64 t, %1; cvt.u32.u64 %0, t; }" : "=r"(a) : "l"(p));
    return a;
}

static __device__ __forceinline__ uint32_t pack_bf16x2(float v0, float v1) {
    __nv_bfloat162 h = __floats2bfloat162_rn(v0, v1);   // .x=v0 (low 16b)
    return *(uint32_t*)&h;
}

// split (v0,v1) into bf16 hi pair + bf16 lo-residual pair
static __device__ __forceinline__ void pack_pair(float v0, float v1,
                                                 uint32_t& h, uint32_t& l) {
    __nv_bfloat162 hh = __floats2bfloat162_rn(v0, v1);
    h = *(uint32_t*)&hh;
    l = pack_bf16x2(v0 - __bfloat162float(hh.x),
                    v1 - __bfloat162float(hh.y));
}

// fast 2^y : magic-rounding + degree-5 poly, FMA/ALU pipes only (no MUFU)
static __device__ __forceinline__ float fast_exp2(float y) {
    y = fmaxf(y, -80.0f);
    const float t = y + 12582912.0f;                    // 1.5 * 2^23
    const int   i = __float_as_int(t);
    const float f = y - (t - 12582912.0f);              // [-0.5, 0.5]
    float p = 0.00133335581f;
    p = fmaf(p, f, 0.00961812911f);
    p = fmaf(p, f, 0.05550410866f);
    p = fmaf(p, f, 0.24022650696f);
    p = fmaf(p, f, 0.69314718056f);
    p = fmaf(p, f, 1.0f);
    return __int_as_float(__float_as_int(p) + (i << 23));
}

#define MMA_BF16(D, A, B0, B1)                                                  \
    asm volatile("mma.sync.aligned.m16n8k16.row.col.f32.bf16.bf16.f32 "         \
                 "{%0,%1,%2,%3}, {%4,%5,%6,%7}, {%8,%9}, {%0,%1,%2,%3};"        \
                 : "+f"((D)[0]), "+f"((D)[1]), "+f"((D)[2]), "+f"((D)[3])       \
                 : "r"((A)[0]), "r"((A)[1]), "r"((A)[2]), "r"((A)[3]),          \
                   "r"(B0), "r"(B1))

#define LDSM_X4_T(R, ADDR)                                                      \
    asm volatile("ldmatrix.sync.aligned.m8n8.x4.trans.shared.b16 "              \
                 "{%0,%1,%2,%3}, [%4];"                                         \
                 : "=r"((R)[0]), "=r"((R)[1]), "=r"((R)[2]), "=r"((R)[3])       \
                 : "r"(ADDR))

#define LDSM_X4(R, ADDR)                                                        \
    asm volatile("ldmatrix.sync.aligned.m8n8.x4.shared.b16 {%0,%1,%2,%3}, [%4];"\
                 : "=r"((R)[0]), "=r"((R)[1]), "=r"((R)[2]), "=r"((R)[3])       \
                 : "r"(ADDR))

#define LDSM_X2(R0, R1, ADDR)                                                   \
    asm volatile("ldmatrix.sync.aligned.m8n8.x2.shared.b16 {%0,%1}, [%2];"      \
                 : "=r"(R0), "=r"(R1) : "r"(ADDR))

#define TEAM_BAR(T) asm volatile("bar.sync %0, 256;" :: "r"((T) + 1) : "memory")

// ---------------------------------------------------------------------------
// Transpose + hi/lo split: x[B][64][N] -> g_xtp[B][N][64] (hi | lo<<16)
// ---------------------------------------------------------------------------
__global__ void transpose_x_kernel(const float* __restrict__ x) {
    __shared__ float tile[32][33];
    const int b  = blockIdx.z;
    const int c0 = blockIdx.y * 32;
    const int n0 = blockIdx.x * 32;
    const int tx = threadIdx.x, ty = threadIdx.y;   // (32, 8)

    const float* xb = x + (size_t)b * CIN * NPTS;
#pragma unroll
    for (int i = 0; i < 4; ++i)
        tile[ty + 8 * i][tx] = xb[(size_t)(c0 + ty + 8 * i) * NPTS + n0 + tx];
    __syncthreads();
    uint32_t* xo = g_xtp + ((size_t)b * NPTS + n0) * CIN;
#pragma unroll
    for (int i = 0; i < 4; ++i) {
        const float v = tile[tx][ty + 8 * i];
        const __nv_bfloat16 h = __float2bfloat16(v);
        const __nv_bfloat16 l = __float2bfloat16(v - __bfloat162float(h));
        const uint32_t w = (uint32_t)*(const uint16_t*)&h
                         | ((uint32_t)*(const uint16_t*)&l << 16);
        xo[(size_t)(ty + 8 * i) * CIN + c0 + tx] = w;
    }
}

// ---------------------------------------------------------------------------
// Fused kernel. 148 persistent CTAs x 512 threads = two independent 8-warp
// TEAMS, each with its own group stream and named barriers.
// Per team-group (4 points):
//   phase 1: warp (2p+h) builds k-half h of point p into the team F tile
//   phase 2: warp w = o-chunk w, all 4 points (2 in flight); 3-MMA bf16
//            hi/lo scores; shfl softmax (FMA exp2); agg -> team agg tile
//   phase 3: warp w: 16 o-channels x 4 points on tensor cores, direct STG
// ---------------------------------------------------------------------------
__global__ __launch_bounds__(NTHREADS, 1)
void randlanet_mma_kernel(const float* __restrict__ pos,
                          const int*   __restrict__ nidx,
                          const float* __restrict__ Wrel,
                          const float* __restrict__ brel,
                          const float* __restrict__ Watt,
                          const float* __restrict__ Wglob,
                          const float* __restrict__ bglob,
                          float*       __restrict__ out) {
    extern __shared__ char smem[];
    float* sWrel  = (float*)(smem + OFF_WREL);
    float* sbrel  = (float*)(smem + OFF_BREL);

    const uint32_t uS = smem_u32(smem);

    const int tid  = threadIdx.x;
    const int warp = tid >> 5;
    const int lane = tid & 31;
    const int gid  = lane >> 2;     // 0..7
    const int qid  = lane & 3;      // 0..3

    const int team = warp >> 3;     // 0 or 1
    const int wt   = warp & 7;      // warp-in-team

    // team-phase roles
    const int pt1 = wt >> 1;        // phase 1: point (0..3)
    const int kh  = wt & 1;         // phase 1: k-half
    const int oc  = wt;             // phase 2: o-chunk

    char* sF = smem + team * TEAM_F;            // team F hi; lo at +F_TILE_T
    const uint32_t uF = uS + (uint32_t)(team * TEAM_F);

    // ---- weights: Wg bf16 hi/lo tiles + Wrel/bias ----
    for (int i = tid; i < CMID * CMID; i += NTHREADS) {
        const int o = i >> 7, c = i & 127;
        const float v = Wglob[c * CMID + o];
        const __nv_bfloat16 h = __float2bfloat16(v);
        const __nv_bfloat16 l = __float2bfloat16(v - __bfloat162float(h));
        *(uint16_t*)(smem + OFF_WGH + o * WG_STRIDE2 + 2 * c) = *(const uint16_t*)&h;
        *(uint16_t*)(smem + OFF_WGL + o * WG_STRIDE2 + 2 * c) = *(const uint16_t*)&l;
    }
    for (int i = tid; i < 10 * DREL; i += NTHREADS) sWrel[i] = Wrel[i];
    if (tid < DREL) sbrel[tid] = brel[tid];

    // ---- W_att A-fragments for o-chunk oc, scaled by log2e, bf16 hi/lo ----
    uint32_t Ahi[8][4], Alo[8][4];
#pragma unroll
    for (int cc = 0; cc < 8; ++cc) {
#pragma unroll
        for (int r = 0; r < 4; ++r) {
            const int o = 16 * oc + gid + (r & 1) * 8;
            const int c = 16 * cc + 2 * qid + (r >> 1) * 8;
            const float v0 = Watt[c * CMID + o] * LOG2E;
            const float v1 = Watt[(c + 1) * CMID + o] * LOG2E;
            pack_pair(v0, v1, Ahi[cc][r], Alo[cc][r]);
        }
    }

    // phase-3 biases (registers)
    const int oP = 16 * wt + 2 * qid;
    const float b00 = bglob[oP],     b01 = bglob[oP + 1];
    const float b10 = bglob[oP + 8], b11 = bglob[oP + 9];
    __syncthreads();

    // phase-2 ldmatrix bases (team F tile)
    uint32_t rowB[8];
#pragma unroll
    for (int cc = 0; cc < 8; ++cc)
        rowB[cc] = uF + (uint32_t)(16 * cc + (lane & 15)) * FSTRIDE
                 + ((lane & 16) ? 16u : 0u);
    const uint32_t aggF = uF + (uint32_t)(16 * oc + (lane & 15)) * FSTRIDE
                        + ((lane & 16) ? 16u : 0u);
    // phase-3 ldmatrix bases
    const uint32_t aAgg = uS + OFF_AGG + (uint32_t)(team * AGG_TEAM)
                        + (uint32_t)(lane & 15) * WG_STRIDE2
                        + ((lane & 16) ? 16u : 0u);
    const uint32_t aWg0 = uS + OFF_WGH
                        + (uint32_t)(16 * wt + (lane & 7)) * WG_STRIDE2
                        + ((lane & 8) ? 16u : 0u);
    const uint32_t aWg1 = aWg0 + 8 * WG_STRIDE2;
    char* aggT = smem + OFF_AGG + team * AGG_TEAM;   // hi; lo at +AGG_TILE2

    for (int g = blockIdx.x * 2 + team; g < G4; g += gridDim.x * 2) {
        const int p0 = g * TP;
        const int bb = p0 >> 14;            // NPTS = 16384
        const int n0 = p0 & (NPTS - 1);

        // ================= phase 1: build k-half of f for point pt1 =======
        {
            const int p = p0 + pt1;
            const int n = p & (NPTS - 1);
            const float* posB = pos + (size_t)bb * NPTS * 3;
            const float cx = posB[n * 3 + 0];
            const float cy = posB[n * 3 + 1];
            const float cz = posB[n * 3 + 2];
            int myidx = 0;
            if (lane < 8) myidx = nidx[(size_t)p * KNN + kh * 8 + lane];
            const uint32_t rowbase = (uint32_t)(pt1 * 32 + kh * 16);

            // ---- pass B: pre-split features, channel rows 64+lane, 96+lane
            {
                uint32_t gh[8], gl[8];
#pragma unroll
                for (int k2 = 0; k2 < 8; k2 += 2) {
                    const int id0 = __shfl_sync(0xffffffffu, myidx, k2);
                    const int id1 = __shfl_sync(0xffffffffu, myidx, k2 + 1);
                    const uint32_t* x0 = g_xtp + ((size_t)bb * NPTS + id0) * CIN;
                    const uint32_t* x1 = g_xtp + ((size_t)bb * NPTS + id1) * CIN;
                    const uint32_t a0 = x0[lane],      a1 = x1[lane];
                    const uint32_t b0 = x0[lane + 32], b1 = x1[lane + 32];
                    gh[k2 >> 1]       = __byte_perm(a0, a1, 0x5410);
                    gl[k2 >> 1]       = __byte_perm(a0, a1, 0x7632);
                    gh[4 + (k2 >> 1)] = __byte_perm(b0, b1, 0x5410);
                    gl[4 + (k2 >> 1)] = __byte_perm(b0, b1, 0x7632);
                }
                const uint32_t r0 = (uint32_t)(64 + lane) * FSTRIDE + rowbase;
                const uint32_t r1 = (uint32_t)(96 + lane) * FSTRIDE + rowbase;
                *(uint4*)(sF + r0)            = make_uint4(gh[0], gh[1], gh[2], gh[3]);
                *(uint4*)(sF + r0 + F_TILE_T) = make_uint4(gl[0], gl[1], gl[2], gl[3]);
                *(uint4*)(sF + r1)            = make_uint4(gh[4], gh[5], gh[6], gh[7]);
                *(uint4*)(sF + r1 + F_TILE_T) = make_uint4(gl[4], gl[5], gl[6], gl[7]);
            }
            // ---- pass A: rel-MLP, channel rows lane, lane+32
            {
                uint32_t gh[8], gl[8];
#pragma unroll
                for (int k2 = 0; k2 < 8; k2 += 2) {
                    float ra[2], rb[2];
#pragma unroll
                    for (int s = 0; s < 2; ++s) {
                        const int id = __shfl_sync(0xffffffffu, myidx, k2 + s);
                        const float nx = posB[id * 3 + 0];
                        const float ny = posB[id * 3 + 1];
                        const float nz = posB[id * 3 + 2];
                        const float rx = nx - cx, ry = ny - cy, rz = nz - cz;
                        const float d  = sqrtf(rx * rx + ry * ry + rz * rz);
                        const float enc[10] = {cx, cy, cz, nx, ny, nz, rx, ry, rz, d};
                        float a0 = sbrel[lane];
                        float a1 = sbrel[lane + 32];
#pragma unroll
                        for (int e = 0; e < 10; ++e) {
                            a0 = fmaf(enc[e], sWrel[e * DREL + lane],      a0);
                            a1 = fmaf(enc[e], sWrel[e * DREL + lane + 32], a1);
                        }
                        ra[s] = fmaxf(a0, 0.0f);
                        rb[s] = fmaxf(a1, 0.0f);
                    }
                    pack_pair(ra[0], ra[1], gh[k2 >> 1],       gl[k2 >> 1]);
                    pack_pair(rb[0], rb[1], gh[4 + (k2 >> 1)], gl[4 + (k2 >> 1)]);
                }
                const uint32_t r0 = (uint32_t)lane * FSTRIDE + rowbase;
                const uint32_t r1 = (uint32_t)(lane + 32) * FSTRIDE + rowbase;
                *(uint4*)(sF + r0)            = make_uint4(gh[0], gh[1], gh[2], gh[3]);
                *(uint4*)(sF + r0 + F_TILE_T) = make_uint4(gl[0], gl[1], gl[2], gl[3]);
                *(uint4*)(sF + r1)            = make_uint4(gh[4], gh[5], gh[6], gh[7]);
                *(uint4*)(sF + r1 + F_TILE_T) = make_uint4(gl[4], gl[5], gl[6], gl[7]);
            }
        }
        TEAM_BAR(team);

        // ================= phase 2: MMA scores + softmax + agg ============
#pragma unroll 1
        for (int pp = 0; pp < 4; pp += 2) {
            const int ptX = pp;
            const int ptY = pp + 1;
            const uint32_t colX = (uint32_t)ptX * 32;
            const uint32_t colY = colX + 32;
            float dAX[4] = {0.f, 0.f, 0.f, 0.f};
            float dBX[4] = {0.f, 0.f, 0.f, 0.f};
            float dAY[4] = {0.f, 0.f, 0.f, 0.f};
            float dBY[4] = {0.f, 0.f, 0.f, 0.f};
#pragma unroll
            for (int cc = 0; cc < 8; ++cc) {
                uint32_t bhX[4], blX[4], bhY[4], blY[4];
                LDSM_X4_T(bhX, rowB[cc] + colX);
                LDSM_X4_T(bhY, rowB[cc] + colY);
                LDSM_X4_T(blX, rowB[cc] + colX + F_TILE_T);
                LDSM_X4_T(blY, rowB[cc] + colY + F_TILE_T);
                MMA_BF16(dAX, Ahi[cc], bhX[0], bhX[1]);
                MMA_BF16(dBX, Ahi[cc], bhX[2], bhX[3]);
                MMA_BF16(dAY, Ahi[cc], bhY[0], bhY[1]);
                MMA_BF16(dBY, Ahi[cc], bhY[2], bhY[3]);
                MMA_BF16(dAX, Ahi[cc], blX[0], blX[1]);
                MMA_BF16(dBX, Ahi[cc], blX[2], blX[3]);
                MMA_BF16(dAY, Ahi[cc], blY[0], blY[1]);
                MMA_BF16(dBY, Ahi[cc], blY[2], blY[3]);
                MMA_BF16(dAX, Alo[cc], bhX[0], bhX[1]);
                MMA_BF16(dBX, Alo[cc], bhX[2], bhX[3]);
                MMA_BF16(dAY, Alo[cc], bhY[0], bhY[1]);
                MMA_BF16(dBY, Alo[cc], bhY[2], bhY[3]);
            }

#pragma unroll
            for (int s = 0; s < 2; ++s) {
                const int pt = s ? ptY : ptX;
                const uint32_t colb = s ? colY : colX;
                float* dA = s ? dAY : dAX;
                float* dB = s ? dBY : dBX;
                float vA[4] = {dA[0], dA[1], dB[0], dB[1]};
                float vB[4] = {dA[2], dA[3], dB[2], dB[3]};

                float mA = fmaxf(fmaxf(vA[0], vA[1]), fmaxf(vA[2], vA[3]));
                float mB = fmaxf(fmaxf(vB[0], vB[1]), fmaxf(vB[2], vB[3]));
                mA = fmaxf(mA, __shfl_xor_sync(0xffffffffu, mA, 1));
                mA = fmaxf(mA, __shfl_xor_sync(0xffffffffu, mA, 2));
                mB = fmaxf(mB, __shfl_xor_sync(0xffffffffu, mB, 1));
                mB = fmaxf(mB, __shfl_xor_sync(0xffffffffu, mB, 2));

                float sA = 0.f, sB = 0.f;
#pragma unroll
                for (int j = 0; j < 4; ++j) {
                    vA[j] = fast_exp2(vA[j] - mA); sA += vA[j];
                    vB[j] = fast_exp2(vB[j] - mB); sB += vB[j];
                }
                sA += __shfl_xor_sync(0xffffffffu, sA, 1);
                sA += __shfl_xor_sync(0xffffffffu, sA, 2);
                sB += __shfl_xor_sync(0xffffffffu, sB, 1);
                sB += __shfl_xor_sync(0xffffffffu, sB, 2);

                uint32_t fh[4], fl[4];
                LDSM_X4(fh, aggF + colb);
                LDSM_X4(fl, aggF + F_TILE_T + colb);

                float aggA, aggB;
                {
                    float2 h, l, f0, f1;
                    h = __bfloat1622float2(*(__nv_bfloat162*)&fh[0]);
                    l = __bfloat1622float2(*(__nv_bfloat162*)&fl[0]);
                    f0.x = h.x + l.x; f0.y = h.y + l.y;
                    h = __bfloat1622float2(*(__nv_bfloat162*)&fh[2]);
                    l = __bfloat1622float2(*(__nv_bfloat162*)&fl[2]);
                    f1.x = h.x + l.x; f1.y = h.y + l.y;
                    aggA = vA[0] * f0.x + vA[1] * f0.y + vA[2] * f1.x + vA[3] * f1.y;

                    h = __bfloat1622float2(*(__nv_bfloat162*)&fh[1]);
                    l = __bfloat1622float2(*(__nv_bfloat162*)&fl[1]);
                    f0.x = h.x + l.x; f0.y = h.y + l.y;
                    h = __bfloat1622float2(*(__nv_bfloat162*)&fh[3]);
                    l = __bfloat1622float2(*(__nv_bfloat162*)&fl[3]);
                    f1.x = h.x + l.x; f1.y = h.y + l.y;
                    aggB = vB[0] * f0.x + vB[1] * f0.y + vB[2] * f1.x + vB[3] * f1.y;
                }
                aggA += __shfl_xor_sync(0xffffffffu, aggA, 1);
                aggA += __shfl_xor_sync(0xffffffffu, aggA, 2);
                aggB += __shfl_xor_sync(0xffffffffu, aggB, 1);
                aggB += __shfl_xor_sync(0xffffffffu, aggB, 2);

                if (qid == 0) {
                    const float wA = aggA / sA;
                    const float wB = aggB / sB;
                    char* rb2 = aggT + pt * WG_STRIDE2;
                    const uint32_t c0b = (uint32_t)(16 * oc + gid) * 2;
                    const __nv_bfloat16 hA = __float2bfloat16(wA);
                    const __nv_bfloat16 lA = __float2bfloat16(wA - __bfloat162float(hA));
                    const __nv_bfloat16 hB = __float2bfloat16(wB);
                    const __nv_bfloat16 lB = __float2bfloat16(wB - __bfloat162float(hB));
                    *(uint16_t*)(rb2 + c0b)                  = *(const uint16_t*)&hA;
                    *(uint16_t*)(rb2 + AGG_TILE2 + c0b)      = *(const uint16_t*)&lA;
                    *(uint16_t*)(rb2 + c0b + 16)             = *(const uint16_t*)&hB;
                    *(uint16_t*)(rb2 + AGG_TILE2 + c0b + 16) = *(const uint16_t*)&lB;
                }
            }
        }
        TEAM_BAR(team);

        // ================= phase 3: out-GEMM on tensor cores ==============
        // warp wt: 4 points x channels 16wt..16wt+15 (two 8-o blocks)
        {
            float dP0[4] = {0.f, 0.f, 0.f, 0.f};
            float dQ0[4] = {0.f, 0.f, 0.f, 0.f};
            float dP1[4] = {0.f, 0.f, 0.f, 0.f};
            float dQ1[4] = {0.f, 0.f, 0.f, 0.f};
#pragma unroll
            for (int cc = 0; cc < 8; ++cc) {
                uint32_t ah[4], al[4];
                uint32_t b0h0, b0h1, b0l0, b0l1, b1h0, b1h1, b1l0, b1l1;
                LDSM_X4(ah, aAgg + cc * 32);
                LDSM_X4(al, aAgg + AGG_TILE2 + cc * 32);
                LDSM_X2(b0h0, b0h1, aWg0 + cc * 32);
                LDSM_X2(b0l0, b0l1, aWg0 + WG_TILE + cc * 32);
                LDSM_X2(b1h0, b1h1, aWg1 + cc * 32);
                LDSM_X2(b1l0, b1l1, aWg1 + WG_TILE + cc * 32);
                MMA_BF16(dP0, ah, b0h0, b0h1);
                MMA_BF16(dP1, ah, b1h0, b1h1);
                MMA_BF16(dQ0, ah, b0l0, b0l1);
                MMA_BF16(dQ1, ah, b1l0, b1l1);
                MMA_BF16(dQ0, al, b0h0, b0h1);
                MMA_BF16(dQ1, al, b1h0, b1h1);
            }
            if (gid < 4) {
                const float r00 = fmaxf(dP0[0] + dQ0[0] + b00, 0.0f);
                const float r01 = fmaxf(dP0[1] + dQ0[1] + b01, 0.0f);
                const float r10 = fmaxf(dP1[0] + dQ1[0] + b10, 0.0f);
                const float r11 = fmaxf(dP1[1] + dQ1[1] + b11, 0.0f);
                float* ob = out + (size_t)bb * COUT * NPTS + n0 + gid;
                ob[(size_t)oP * NPTS]       = r00;
                ob[(size_t)(oP + 1) * NPTS] = r01;
                ob[(size_t)(oP + 8) * NPTS] = r10;
                ob[(size_t)(oP + 9) * NPTS] = r11;
            }
        }
        // no team barrier here: per-warp order ph3 -> ph1 -> bar -> ph2
        // guarantees agg reads complete before the next group's agg writes,
        // and F reads (all in ph2) completed before the bar above.
    }
}

// ---------------------------------------------------------------------------
extern "C" void kernel_launch(void* const* d_in, const int* in_sizes, int n_in,
                              void* d_out, int out_size) {
    const float* x     = (const float*)d_in[0];
    const float* pos   = (const float*)d_in[1];
    const int*   nidx  = (const int*)  d_in[2];
    const float* Wrel  = (const float*)d_in[3];
    const float* brel  = (const float*)d_in[4];
    const float* Watt  = (const float*)d_in[5];
    const float* Wglob = (const float*)d_in[6];
    const float* bglob = (const float*)d_in[7];
    float*       out   = (float*)d_out;

    transpose_x_kernel<<<dim3(NPTS / 32, CIN / 32, BATCH), dim3(32, 8)>>>(x);

    cudaFuncSetAttribute(randlanet_mma_kernel,
                         cudaFuncAttributeMaxDynamicSharedMemorySize, SMEM_BYTES);
    randlanet_mma_kernel<<<148, NTHREADS, SMEM_BYTES>>>(pos, nidx, Wrel, brel,
                                                        Watt, Wglob, bglob, out);
}

// round 14
// speedup vs baseline: 1.0586x; 1.0586x over previous
#include <cuda_runtime.h>
#include <cuda_bf16.h>
#include <cstdint>

// Problem constants
#define BATCH 4
#define NPTS  16384
#define KNN   16
#define CIN   64
#define DREL  64
#define CMID  128
#define COUT  128
#define GROUPS ((BATCH * NPTS) / 8)   // 8192 groups of 8 points
#define LOG2E 1.4426950408889634f
#define NTHREADS 512

// ---------------------------------------------------------------------------
// SMEM layout (bytes)
//   Fhi/Flo   : [128 c rows][128 pk cols] bf16, row stride 272B
//   WgThi/lo  : [128 o rows][128 c cols] bf16, row stride 272B (out-GEMM B)
//   Wrel fp32, brel, bglob
//   AggHi/Lo  : [2 parity][16 rows (8 pts used)][128 c] bf16, stride 272B
// ---------------------------------------------------------------------------
#define F_ROWSTRIDE 272
#define F_TILE      (128 * F_ROWSTRIDE + 64)     // 34880
#define OFF_FHI     0
#define OFF_FLO     F_TILE
#define OFF_WGH     (2 * F_TILE)                 // 69760
#define OFF_WGL     (OFF_WGH + F_TILE)           // 104640
#define OFF_WREL    (OFF_WGL + F_TILE)           // 139520
#define OFF_BREL    (OFF_WREL + 2560)
#define OFF_BGLOB   (OFF_BREL + 256)
#define OFF_AGG     (OFF_BGLOB + 512)            // 142848
#define AGG_TILE    (16 * F_ROWSTRIDE)           // 4352 (hi); lo at +4352
#define AGG_PAR     (2 * AGG_TILE)               // 8704 per parity
#define SMEM_BYTES  (OFF_AGG + 2 * AGG_PAR)      // 160256

// Scratch: packed bf16 hi/lo of transposed features: word = hi | (lo<<16)
__device__ uint32_t g_xtp[BATCH * NPTS * CIN];

// ---------------------------------------------------------------------------
static __device__ __forceinline__ uint32_t smem_u32(const void* p) {
    uint32_t a;
    asm("{ .reg .u64 t; cvta.to.shared.u64 t, %1; cvt.u32.u64 %0, t; }" : "=r"(a) : "l"(p));
    return a;
}

static __device__ __forceinline__ uint32_t frow(int c) {
    return (uint32_t)(c * F_ROWSTRIDE);
}

static __device__ __forceinline__ uint32_t pack_bf16x2(float v0, float v1) {
    __nv_bfloat162 h = __floats2bfloat162_rn(v0, v1);   // .x=v0 (low 16b)
    return *(uint32_t*)&h;
}

// split (v0,v1) into bf16 hi pair + bf16 lo-residual pair
static __device__ __forceinline__ void pack_pair(float v0, float v1,
                                                 uint32_t& h, uint32_t& l) {
    __nv_bfloat162 hh = __floats2bfloat162_rn(v0, v1);
    h = *(uint32_t*)&hh;
    l = pack_bf16x2(v0 - __bfloat162float(hh.x),
                    v1 - __bfloat162float(hh.y));
}

// fast 2^y : magic-rounding + degree-5 poly, FMA/ALU pipes only (no MUFU)
static __device__ __forceinline__ float fast_exp2(float y) {
    y = fmaxf(y, -80.0f);
    const float t = y + 12582912.0f;                    // 1.5 * 2^23
    const int   i = __float_as_int(t);
    const float f = y - (t - 12582912.0f);              // [-0.5, 0.5]
    float p = 0.00133335581f;
    p = fmaf(p, f, 0.00961812911f);
    p = fmaf(p, f, 0.05550410866f);
    p = fmaf(p, f, 0.24022650696f);
    p = fmaf(p, f, 0.69314718056f);
    p = fmaf(p, f, 1.0f);
    return __int_as_float(__float_as_int(p) + (i << 23));
}

// NOTE: MMA is a pure register op — NON-volatile, no memory clobber, so ptxas
// may schedule it freely around loads (software pipelining the cc loop).
#define MMA_BF16(D, A, B0, B1)                                                  \
    asm("mma.sync.aligned.m16n8k16.row.col.f32.bf16.bf16.f32 "                  \
        "{%0,%1,%2,%3}, {%4,%5,%6,%7}, {%8,%9}, {%0,%1,%2,%3};"                 \
        : "+f"((D)[0]), "+f"((D)[1]), "+f"((D)[2]), "+f"((D)[3])                \
        : "r"((A)[0]), "r"((A)[1]), "r"((A)[2]), "r"((A)[3]),                   \
          "r"(B0), "r"(B1))

// LDSM: non-volatile but with memory clobber — ordered vs stores/barriers,
// still reorderable relative to MMAs (register ops).
#define LDSM_X4_T(R, ADDR)                                                      \
    asm("ldmatrix.sync.aligned.m8n8.x4.trans.shared.b16 "                       \
        "{%0,%1,%2,%3}, [%4];"                                                  \
        : "=r"((R)[0]), "=r"((R)[1]), "=r"((R)[2]), "=r"((R)[3])                \
        : "r"(ADDR) : "memory")

#define LDSM_X4(R, ADDR)                                                        \
    asm("ldmatrix.sync.aligned.m8n8.x4.shared.b16 {%0,%1,%2,%3}, [%4];"         \
        : "=r"((R)[0]), "=r"((R)[1]), "=r"((R)[2]), "=r"((R)[3])                \
        : "r"(ADDR) : "memory")

#define LDSM_X2(R0, R1, ADDR)                                                   \
    asm("ldmatrix.sync.aligned.m8n8.x2.shared.b16 {%0,%1}, [%2];"               \
        : "=r"(R0), "=r"(R1) : "r"(ADDR) : "memory")

// ---------------------------------------------------------------------------
// Transpose + hi/lo split: x[B][64][N] -> g_xtp[B][N][64] (hi | lo<<16)
// ---------------------------------------------------------------------------
__global__ void transpose_x_kernel(const float* __restrict__ x) {
    __shared__ float tile[32][33];
    const int b  = blockIdx.z;
    const int c0 = blockIdx.y * 32;
    const int n0 = blockIdx.x * 32;
    const int tx = threadIdx.x, ty = threadIdx.y;   // (32, 8)

    const float* xb = x + (size_t)b * CIN * NPTS;
#pragma unroll
    for (int i = 0; i < 4; ++i)
        tile[ty + 8 * i][tx] = xb[(size_t)(c0 + ty + 8 * i) * NPTS + n0 + tx];
    __syncthreads();
    uint32_t* xo = g_xtp + ((size_t)b * NPTS + n0) * CIN;
#pragma unroll
    for (int i = 0; i < 4; ++i) {
        const float v = tile[tx][ty + 8 * i];
        const __nv_bfloat16 h = __float2bfloat16(v);
        const __nv_bfloat16 l = __float2bfloat16(v - __bfloat162float(h));
        const uint32_t w = (uint32_t)*(const uint16_t*)&h
                         | ((uint32_t)*(const uint16_t*)&l << 16);
        xo[(size_t)(ty + 8 * i) * CIN + c0 + tx] = w;
    }
}

// ---------------------------------------------------------------------------
// Fused kernel. 148 persistent CTAs x 512 threads (16 warps). R12 structure
// (best so far) with non-volatile MMA/LDSM for compiler software pipelining.
// ---------------------------------------------------------------------------
__global__ __launch_bounds__(NTHREADS, 1)
void randlanet_mma_kernel(const float* __restrict__ pos,
                          const int*   __restrict__ nidx,
                          const float* __restrict__ Wrel,
                          const float* __restrict__ brel,
                          const float* __restrict__ Watt,
                          const float* __restrict__ Wglob,
                          const float* __restrict__ bglob,
                          float*       __restrict__ out) {
    extern __shared__ char smem[];
    char*  sFhi    = smem + OFF_FHI;
    char*  sFlo    = smem + OFF_FLO;
    float* sWrel   = (float*)(smem + OFF_WREL);
    float* sbrel   = (float*)(smem + OFF_BREL);
    float* sbglob  = (float*)(smem + OFF_BGLOB);

    const uint32_t uS   = smem_u32(smem);
    const uint32_t uFhi = uS + OFF_FHI;

    const int tid  = threadIdx.x;
    const int warp = tid >> 5;
    const int lane = tid & 31;
    const int gid  = lane >> 2;     // 0..7
    const int qid  = lane & 3;      // 0..3

    // phase-role indices
    const int pt1   = warp >> 1;        // phase 1: point
    const int kh    = warp & 1;         // phase 1: k-half
    const int oc    = warp & 7;         // phase 2: o-chunk
    const int pbase = (warp >> 3) * 4;  // phase 2: first point

    // ---- weights: WgT bf16 hi/lo tiles + Wrel/bias fp32 ----
    for (int i = tid; i < CMID * CMID; i += NTHREADS) {
        const int o = i >> 7, c = i & 127;
        const float v = Wglob[c * CMID + o];
        const __nv_bfloat16 h = __float2bfloat16(v);
        const __nv_bfloat16 l = __float2bfloat16(v - __bfloat162float(h));
        *(uint16_t*)(smem + OFF_WGH + frow(o) + 2 * c) = *(const uint16_t*)&h;
        *(uint16_t*)(smem + OFF_WGL + frow(o) + 2 * c) = *(const uint16_t*)&l;
    }
    for (int i = tid; i < 10 * DREL; i += NTHREADS) sWrel[i] = Wrel[i];
    if (tid < DREL) sbrel[tid]  = brel[tid];
    if (tid < COUT) sbglob[tid] = bglob[tid];

    // ---- W_att A-fragments for o-chunk oc, scaled by log2e, bf16 hi/lo ----
    uint32_t Ahi[8][4], Alo[8][4];
#pragma unroll
    for (int cc = 0; cc < 8; ++cc) {
#pragma unroll
        for (int r = 0; r < 4; ++r) {
            const int o = 16 * oc + gid + (r & 1) * 8;
            const int c = 16 * cc + 2 * qid + (r >> 1) * 8;
            const float v0 = Watt[c * CMID + o] * LOG2E;
            const float v1 = Watt[(c + 1) * CMID + o] * LOG2E;
            pack_pair(v0, v1, Ahi[cc][r], Alo[cc][r]);
        }
    }
    __syncthreads();

    // phase-2 ldmatrix bases
    uint32_t rowB[8];
#pragma unroll
    for (int cc = 0; cc < 8; ++cc)
        rowB[cc] = uFhi + frow(16 * cc + (lane & 15)) + ((lane & 16) ? 16u : 0u);
    const uint32_t aggHiB = uFhi + frow(16 * oc + (lane & 15))
                          + ((lane & 16) ? 16u : 0u);
    // phase-3 ldmatrix bases
    const uint32_t aAgg0 = uS + OFF_AGG + (uint32_t)(lane & 15) * F_ROWSTRIDE
                         + ((lane & 16) ? 16u : 0u);
    const uint32_t aWg   = uS + OFF_WGH
                         + (uint32_t)(8 * warp + (lane & 7)) * F_ROWSTRIDE
                         + ((lane & 8) ? 16u : 0u);
    const int oP = 8 * warp + 2 * qid;            // phase 3: output channels
    const float bias0 = bglob[oP];
    const float bias1 = bglob[oP + 1];

    for (int g = blockIdx.x; g < GROUPS; g += gridDim.x) {
        const int p0  = g * 8;
        const int par = (g / gridDim.x) & 1;
        const uint32_t aggBase = (uint32_t)(OFF_AGG + par * AGG_PAR);
        const int bb = p0 >> 14;            // NPTS = 16384
        const int n0 = p0 & (NPTS - 1);

        // ================= phase 1: build k-half of f for point pt1 =======
        {
            const int p = p0 + pt1;
            const int n = (p & (NPTS - 1));
            const float* posB = pos + (size_t)bb * NPTS * 3;
            const float cx = posB[n * 3 + 0];
            const float cy = posB[n * 3 + 1];
            const float cz = posB[n * 3 + 2];
            int myidx = 0;
            if (lane < 8) myidx = nidx[(size_t)p * KNN + kh * 8 + lane];
            const uint32_t rowbase = (uint32_t)(pt1 * 32 + kh * 16);

            // ---- pass B: pre-split features, channel rows 64+lane, 96+lane
            {
                uint32_t gh[8], gl[8];
#pragma unroll
                for (int k2 = 0; k2 < 8; k2 += 2) {
                    const int id0 = __shfl_sync(0xffffffffu, myidx, k2);
                    const int id1 = __shfl_sync(0xffffffffu, myidx, k2 + 1);
                    const uint32_t* x0 = g_xtp + ((size_t)bb * NPTS + id0) * CIN;
                    const uint32_t* x1 = g_xtp + ((size_t)bb * NPTS + id1) * CIN;
                    const uint32_t a0 = x0[lane],      a1 = x1[lane];
                    const uint32_t b0 = x0[lane + 32], b1 = x1[lane + 32];
                    gh[k2 >> 1]       = __byte_perm(a0, a1, 0x5410);
                    gl[k2 >> 1]       = __byte_perm(a0, a1, 0x7632);
                    gh[4 + (k2 >> 1)] = __byte_perm(b0, b1, 0x5410);
                    gl[4 + (k2 >> 1)] = __byte_perm(b0, b1, 0x7632);
                }
                const uint32_t r0 = frow(64 + lane) + rowbase;
                const uint32_t r1 = frow(96 + lane) + rowbase;
                *(uint4*)(sFhi + r0) = make_uint4(gh[0], gh[1], gh[2], gh[3]);
                *(uint4*)(sFlo + r0) = make_uint4(gl[0], gl[1], gl[2], gl[3]);
                *(uint4*)(sFhi + r1) = make_uint4(gh[4], gh[5], gh[6], gh[7]);
                *(uint4*)(sFlo + r1) = make_uint4(gl[4], gl[5], gl[6], gl[7]);
            }
            // ---- pass A: rel-MLP, channel rows lane, lane+32
            {
                uint32_t gh[8], gl[8];
#pragma unroll
                for (int k2 = 0; k2 < 8; k2 += 2) {
                    float ra[2], rb[2];
#pragma unroll
                    for (int s = 0; s < 2; ++s) {
                        const int id = __shfl_sync(0xffffffffu, myidx, k2 + s);
                        const float nx = posB[id * 3 + 0];
                        const float ny = posB[id * 3 + 1];
                        const float nz = posB[id * 3 + 2];
                        const float rx = nx - cx, ry = ny - cy, rz = nz - cz;
                        const float d  = sqrtf(rx * rx + ry * ry + rz * rz);
                        const float enc[10] = {cx, cy, cz, nx, ny, nz, rx, ry, rz, d};
                        float a0 = sbrel[lane];
                        float a1 = sbrel[lane + 32];
#pragma unroll
                        for (int e = 0; e < 10; ++e) {
                            a0 = fmaf(enc[e], sWrel[e * DREL + lane],      a0);
                            a1 = fmaf(enc[e], sWrel[e * DREL + lane + 32], a1);
                        }
                        ra[s] = fmaxf(a0, 0.0f);
                        rb[s] = fmaxf(a1, 0.0f);
                    }
                    pack_pair(ra[0], ra[1], gh[k2 >> 1],       gl[k2 >> 1]);
                    pack_pair(rb[0], rb[1], gh[4 + (k2 >> 1)], gl[4 + (k2 >> 1)]);
                }
                const uint32_t r0 = frow(lane) + rowbase;
                const uint32_t r1 = frow(lane + 32) + rowbase;
                *(uint4*)(sFhi + r0) = make_uint4(gh[0], gh[1], gh[2], gh[3]);
                *(uint4*)(sFlo + r0) = make_uint4(gl[0], gl[1], gl[2], gl[3]);
                *(uint4*)(sFhi + r1) = make_uint4(gh[4], gh[5], gh[6], gh[7]);
                *(uint4*)(sFlo + r1) = make_uint4(gl[4], gl[5], gl[6], gl[7]);
            }
        }
        __syncthreads();

        // ================= phase 2: MMA scores + softmax + agg ============
#pragma unroll 1
        for (int pp = 0; pp < 4; pp += 2) {
            const int ptX = pbase + pp;
            const int ptY = ptX + 1;
            const uint32_t colX = (uint32_t)ptX * 32;
            const uint32_t colY = colX + 32;
            float dAX[4] = {0.f, 0.f, 0.f, 0.f};
            float dBX[4] = {0.f, 0.f, 0.f, 0.f};
            float dAY[4] = {0.f, 0.f, 0.f, 0.f};
            float dBY[4] = {0.f, 0.f, 0.f, 0.f};
#pragma unroll
            for (int cc = 0; cc < 8; ++cc) {
                uint32_t bhX[4], blX[4], bhY[4], blY[4];
                LDSM_X4_T(bhX, rowB[cc] + colX);
                LDSM_X4_T(bhY, rowB[cc] + colY);
                LDSM_X4_T(blX, rowB[cc] + colX + F_TILE);
                LDSM_X4_T(blY, rowB[cc] + colY + F_TILE);
                MMA_BF16(dAX, Ahi[cc], bhX[0], bhX[1]);
                MMA_BF16(dBX, Ahi[cc], bhX[2], bhX[3]);
                MMA_BF16(dAY, Ahi[cc], bhY[0], bhY[1]);
                MMA_BF16(dBY, Ahi[cc], bhY[2], bhY[3]);
                MMA_BF16(dAX, Ahi[cc], blX[0], blX[1]);
                MMA_BF16(dBX, Ahi[cc], blX[2], blX[3]);
                MMA_BF16(dAY, Ahi[cc], blY[0], blY[1]);
                MMA_BF16(dBY, Ahi[cc], blY[2], blY[3]);
                MMA_BF16(dAX, Alo[cc], bhX[0], bhX[1]);
                MMA_BF16(dBX, Alo[cc], bhX[2], bhX[3]);
                MMA_BF16(dAY, Alo[cc], bhY[0], bhY[1]);
                MMA_BF16(dBY, Alo[cc], bhY[2], bhY[3]);
            }

#pragma unroll
            for (int s = 0; s < 2; ++s) {
                const int pt = s ? ptY : ptX;
                const uint32_t colb = s ? colY : colX;
                float* dA = s ? dAY : dAX;
                float* dB = s ? dBY : dBX;
                float vA[4] = {dA[0], dA[1], dB[0], dB[1]};
                float vB[4] = {dA[2], dA[3], dB[2], dB[3]};

                float mA = fmaxf(fmaxf(vA[0], vA[1]), fmaxf(vA[2], vA[3]));
                float mB = fmaxf(fmaxf(vB[0], vB[1]), fmaxf(vB[2], vB[3]));
                mA = fmaxf(mA, __shfl_xor_sync(0xffffffffu, mA, 1));
                mA = fmaxf(mA, __shfl_xor_sync(0xffffffffu, mA, 2));
                mB = fmaxf(mB, __shfl_xor_sync(0xffffffffu, mB, 1));
                mB = fmaxf(mB, __shfl_xor_sync(0xffffffffu, mB, 2));

                float sA = 0.f, sB = 0.f;
#pragma unroll
                for (int j = 0; j < 4; ++j) {
                    vA[j] = fast_exp2(vA[j] - mA); sA += vA[j];
                    vB[j] = fast_exp2(vB[j] - mB); sB += vB[j];
                }
                sA += __shfl_xor_sync(0xffffffffu, sA, 1);
                sA += __shfl_xor_sync(0xffffffffu, sA, 2);
                sB += __shfl_xor_sync(0xffffffffu, sB, 1);
                sB += __shfl_xor_sync(0xffffffffu, sB, 2);

                uint32_t fh[4], fl[4];
                LDSM_X4(fh, aggHiB + colb);
                LDSM_X4(fl, aggHiB + F_TILE + colb);

                float aggA, aggB;
                {
                    float2 h, l, f0, f1;
                    h = __bfloat1622float2(*(__nv_bfloat162*)&fh[0]);
                    l = __bfloat1622float2(*(__nv_bfloat162*)&fl[0]);
                    f0.x = h.x + l.x; f0.y = h.y + l.y;
                    h = __bfloat1622float2(*(__nv_bfloat162*)&fh[2]);
                    l = __bfloat1622float2(*(__nv_bfloat162*)&fl[2]);
                    f1.x = h.x + l.x; f1.y = h.y + l.y;
                    aggA = vA[0] * f0.x + vA[1] * f0.y + vA[2] * f1.x + vA[3] * f1.y;

                    h = __bfloat1622float2(*(__nv_bfloat162*)&fh[1]);
                    l = __bfloat1622float2(*(__nv_bfloat162*)&fl[1]);
                    f0.x = h.x + l.x; f0.y = h.y + l.y;
                    h = __bfloat1622float2(*(__nv_bfloat162*)&fh[3]);
                    l = __bfloat1622float2(*(__nv_bfloat162*)&fl[3]);
                    f1.x = h.x + l.x; f1.y = h.y + l.y;
                    aggB = vB[0] * f0.x + vB[1] * f0.y + vB[2] * f1.x + vB[3] * f1.y;
                }
                aggA += __shfl_xor_sync(0xffffffffu, aggA, 1);
                aggA += __shfl_xor_sync(0xffffffffu, aggA, 2);
                aggB += __shfl_xor_sync(0xffffffffu, aggB, 1);
                aggB += __shfl_xor_sync(0xffffffffu, aggB, 2);

                if (qid == 0) {
                    const float wA = aggA / sA;
                    const float wB = aggB / sB;
                    const uint32_t rb2 = aggBase + (uint32_t)pt * F_ROWSTRIDE;
                    const uint32_t c0b = (uint32_t)(16 * oc + gid) * 2;
                    const __nv_bfloat16 hA = __float2bfloat16(wA);
                    const __nv_bfloat16 lA = __float2bfloat16(wA - __bfloat162float(hA));
                    const __nv_bfloat16 hB = __float2bfloat16(wB);
                    const __nv_bfloat16 lB = __float2bfloat16(wB - __bfloat162float(hB));
                    *(uint16_t*)(smem + rb2 + c0b)                  = *(const uint16_t*)&hA;
                    *(uint16_t*)(smem + rb2 + AGG_TILE + c0b)       = *(const uint16_t*)&lA;
                    *(uint16_t*)(smem + rb2 + c0b + 16)             = *(const uint16_t*)&hB;
                    *(uint16_t*)(smem + rb2 + AGG_TILE + c0b + 16)  = *(const uint16_t*)&lB;
                }
            }
        }
        __syncthreads();

        // ================= phase 3: out-GEMM on tensor cores ==============
        // warp w: all 8 points x channels 8w..8w+7; D rows 8-15 ignored
        {
            const uint32_t aA = aAgg0 + (uint32_t)(par * AGG_PAR);
            float dP[4] = {0.f, 0.f, 0.f, 0.f};
            float dQ[4] = {0.f, 0.f, 0.f, 0.f};
#pragma unroll
            for (int cc = 0; cc < 8; ++cc) {
                uint32_t ah[4], al[4], bh0, bh1, bl0, bl1;
                LDSM_X4(ah, aA + cc * 32);
                LDSM_X4(al, aA + AGG_TILE + cc * 32);
                LDSM_X2(bh0, bh1, aWg + cc * 32);
                LDSM_X2(bl0, bl1, aWg + F_TILE + cc * 32);
                MMA_BF16(dP, ah, bh0, bh1);
                MMA_BF16(dQ, ah, bl0, bl1);
                MMA_BF16(dQ, al, bh0, bh1);
            }
            const float r0 = fmaxf(dP[0] + dQ[0] + bias0, 0.0f);
            const float r1 = fmaxf(dP[1] + dQ[1] + bias1, 0.0f);
            float* ob = out + (size_t)bb * COUT * NPTS + n0 + gid;
            ob[(size_t)oP * NPTS]       = r0;
            ob[(size_t)(oP + 1) * NPTS] = r1;
        }
        // no barrier: next phase 1 only writes F; phase-2 agg writes are
        // parity-buffered and gated by the post-phase-1 barrier
    }
}

// ---------------------------------------------------------------------------
extern "C" void kernel_launch(void* const* d_in, const int* in_sizes, int n_in,
                              void* d_out, int out_size) {
    const float* x     = (const float*)d_in[0];
    const float* pos   = (const float*)d_in[1];
    const int*   nidx  = (const int*)  d_in[2];
    const float* Wrel  = (const float*)d_in[3];
    const float* brel  = (const float*)d_in[4];
    const float* Watt  = (const float*)d_in[5];
    const float* Wglob = (const float*)d_in[6];
    const float* bglob = (const float*)d_in[7];
    float*       out   = (float*)d_out;

    transpose_x_kernel<<<dim3(NPTS / 32, CIN / 32, BATCH), dim3(32, 8)>>>(x);

    cudaFuncSetAttribute(randlanet_mma_kernel,
                         cudaFuncAttributeMaxDynamicSharedMemorySize, SMEM_BYTES);
    randlanet_mma_kernel<<<148, NTHREADS, SMEM_BYTES>>>(pos, nidx, Wrel, brel,
                                                        Watt, Wglob, bglob, out);
}

// round 17
// speedup vs baseline: 1.0638x; 1.0049x over previous
#include <cuda_runtime.h>
#include <cuda_bf16.h>
#include <cstdint>

// Problem constants
#define BATCH 4
#define NPTS  16384
#define KNN   16
#define CIN   64
#define DREL  64
#define CMID  128
#define COUT  128
#define GROUPS ((BATCH * NPTS) / 8)   // 8192 groups of 8 points
#define LOG2E 1.4426950408889634f
#define NTHREADS 512

// ---------------------------------------------------------------------------
// SMEM layout (bytes)
//   F[2 buffers] : each hi+lo [128 c rows][128 pk cols] bf16, stride 272B
//   WgThi/lo     : [128 o rows][128 c] bf16, stride 272B
//   Wrel fp32, brel, bglob
//   Agg[2 parity]: hi+lo [8 pt rows][128 c] bf16, stride 272B
// ---------------------------------------------------------------------------
#define F_ROWSTRIDE 272
#define F_TILE      (128 * F_ROWSTRIDE)          // 34816
#define OFF_WGH     (4 * F_TILE)                 // 139264
#define OFF_WGL     (OFF_WGH + F_TILE)           // 174080
#define OFF_WREL    (OFF_WGL + F_TILE)           // 208896
#define OFF_BREL    (OFF_WREL + 2560)
#define OFF_BGLOB   (OFF_BREL + 256)
#define OFF_AGG     (OFF_BGLOB + 512)            // 212224
#define AGG_TILE    (8 * F_ROWSTRIDE)            // 2176 (hi); lo at +2176
#define AGG_PAR     (2 * AGG_TILE)               // 4352 per parity
#define SMEM_BYTES  (OFF_AGG + 2 * AGG_PAR)      // 220928

// Scratch: packed bf16 hi/lo of transposed features: word = hi | (lo<<16)
__device__ uint32_t g_xtp[BATCH * NPTS * CIN];

// ---------------------------------------------------------------------------
static __device__ __forceinline__ uint32_t smem_u32(const void* p) {
    uint32_t a;
    asm("{ .reg .u64 t; cvta.to.shared.u64 t, %1; cvt.u32.u64 %0, t; }" : "=r"(a) : "l"(p));
    return a;
}

static __device__ __forceinline__ uint32_t frow(int c) {
    return (uint32_t)(c * F_ROWSTRIDE);
}

static __device__ __forceinline__ uint32_t pack_bf16x2(float v0, float v1) {
    __nv_bfloat162 h = __floats2bfloat162_rn(v0, v1);   // .x=v0 (low 16b)
    return *(uint32_t*)&h;
}

// split (v0,v1) into bf16 hi pair + bf16 lo-residual pair
static __device__ __forceinline__ void pack_pair(float v0, float v1,
                                                 uint32_t& h, uint32_t& l) {
    __nv_bfloat162 hh = __floats2bfloat162_rn(v0, v1);
    h = *(uint32_t*)&hh;
    l = pack_bf16x2(v0 - __bfloat162float(hh.x),
                    v1 - __bfloat162float(hh.y));
}

// fast 2^y : magic-rounding + degree-5 poly, FMA/ALU pipes only (no MUFU)
static __device__ __forceinline__ float fast_exp2(float y) {
    y = fmaxf(y, -80.0f);
    const float t = y + 12582912.0f;                    // 1.5 * 2^23
    const int   i = __float_as_int(t);
    const float f = y - (t - 12582912.0f);              // [-0.5, 0.5]
    float p = 0.00133335581f;
    p = fmaf(p, f, 0.00961812911f);
    p = fmaf(p, f, 0.05550410866f);
    p = fmaf(p, f, 0.24022650696f);
    p = fmaf(p, f, 0.69314718056f);
    p = fmaf(p, f, 1.0f);
    return __int_as_float(__float_as_int(p) + (i << 23));
}

#define MMA_BF16(D, A, B0, B1)                                                  \
    asm("mma.sync.aligned.m16n8k16.row.col.f32.bf16.bf16.f32 "                  \
        "{%0,%1,%2,%3}, {%4,%5,%6,%7}, {%8,%9}, {%0,%1,%2,%3};"                 \
        : "+f"((D)[0]), "+f"((D)[1]), "+f"((D)[2]), "+f"((D)[3])                \
        : "r"((A)[0]), "r"((A)[1]), "r"((A)[2]), "r"((A)[3]),                   \
          "r"(B0), "r"(B1))

#define LDSM_X4_T(R, ADDR)                                                      \
    asm("ldmatrix.sync.aligned.m8n8.x4.trans.shared.b16 "                       \
        "{%0,%1,%2,%3}, [%4];"                                                  \
        : "=r"((R)[0]), "=r"((R)[1]), "=r"((R)[2]), "=r"((R)[3])                \
        : "r"(ADDR) : "memory")

#define LDSM_X4(R, ADDR)                                                        \
    asm("ldmatrix.sync.aligned.m8n8.x4.shared.b16 {%0,%1,%2,%3}, [%4];"         \
        : "=r"((R)[0]), "=r"((R)[1]), "=r"((R)[2]), "=r"((R)[3])                \
        : "r"(ADDR) : "memory")

#define LDSM_X2(R0, R1, ADDR)                                                   \
    asm("ldmatrix.sync.aligned.m8n8.x2.shared.b16 {%0,%1}, [%2];"               \
        : "=r"(R0), "=r"(R1) : "r"(ADDR) : "memory")

// ---------------------------------------------------------------------------
// Transpose + hi/lo split: x[B][64][N] -> g_xtp[B][N][64] (hi | lo<<16)
// ---------------------------------------------------------------------------
__global__ void transpose_x_kernel(const float* __restrict__ x) {
    __shared__ float tile[32][33];
    const int b  = blockIdx.z;
    const int c0 = blockIdx.y * 32;
    const int n0 = blockIdx.x * 32;
    const int tx = threadIdx.x, ty = threadIdx.y;   // (32, 8)

    const float* xb = x + (size_t)b * CIN * NPTS;
#pragma unroll
    for (int i = 0; i < 4; ++i)
        tile[ty + 8 * i][tx] = xb[(size_t)(c0 + ty + 8 * i) * NPTS + n0 + tx];
    __syncthreads();
    uint32_t* xo = g_xtp + ((size_t)b * NPTS + n0) * CIN;
#pragma unroll
    for (int i = 0; i < 4; ++i) {
        const float v = tile[tx][ty + 8 * i];
        const __nv_bfloat16 h = __float2bfloat16(v);
        const __nv_bfloat16 l = __float2bfloat16(v - __bfloat162float(h));
        const uint32_t w = (uint32_t)*(const uint16_t*)&h
                         | ((uint32_t)*(const uint16_t*)&l << 16);
        xo[(size_t)(ty + 8 * i) * CIN + c0 + tx] = w;
    }
}

// ---------------------------------------------------------------------------
// Fused kernel. 148 persistent CTAs x 512 threads (16 warps).
// F DOUBLE-BUFFERED; ONE barrier per group:
//   iter: ph1(g+step -> F[b^1]); ph2(g <- F[b]) -> agg[par]; bar; ph3(g)
// ---------------------------------------------------------------------------
__global__ __launch_bounds__(NTHREADS, 1)
void randlanet_mma_kernel(const float* __restrict__ pos,
                          const int*   __restrict__ nidx,
                          const float* __restrict__ Wrel,
                          const float* __restrict__ brel,
                          const float* __restrict__ Watt,
                          const float* __restrict__ Wglob,
                          const float* __restrict__ bglob,
                          float*       __restrict__ out) {
    extern __shared__ char smem[];
    float* sWrel   = (float*)(smem + OFF_WREL);
    float* sbrel   = (float*)(smem + OFF_BREL);
    float* sbglob  = (float*)(smem + OFF_BGLOB);

    const uint32_t uS = smem_u32(smem);

    const int tid  = threadIdx.x;
    const int warp = tid >> 5;
    const int lane = tid & 31;
    const int gid  = lane >> 2;     // 0..7
    const int qid  = lane & 3;      // 0..3

    // phase-role indices
    const int pt1   = warp >> 1;        // phase 1: point
    const int kh    = warp & 1;         // phase 1: k-half
    const int oc    = warp & 7;         // phase 2: o-chunk
    const int pbase = (warp >> 3) * 4;  // phase 2: first point

    // ---- weights: WgT bf16 hi/lo tiles + Wrel/bias fp32 ----
    for (int i = tid; i < CMID * CMID; i += NTHREADS) {
        const int o = i >> 7, c = i & 127;
        const float v = Wglob[c * CMID + o];
        const __nv_bfloat16 h = __float2bfloat16(v);
        const __nv_bfloat16 l = __float2bfloat16(v - __bfloat162float(h));
        *(uint16_t*)(smem + OFF_WGH + frow(o) + 2 * c) = *(const uint16_t*)&h;
        *(uint16_t*)(smem + OFF_WGL + frow(o) + 2 * c) = *(const uint16_t*)&l;
    }
    for (int i = tid; i < 10 * DREL; i += NTHREADS) sWrel[i] = Wrel[i];
    if (tid < DREL) sbrel[tid]  = brel[tid];
    if (tid < COUT) sbglob[tid] = bglob[tid];

    // ---- W_att A-fragments for o-chunk oc, scaled by log2e, bf16 hi/lo ----
    uint32_t Ahi[8][4], Alo[8][4];
#pragma unroll
    for (int cc = 0; cc < 8; ++cc) {
#pragma unroll
        for (int r = 0; r < 4; ++r) {
            const int o = 16 * oc + gid + (r & 1) * 8;
            const int c = 16 * cc + 2 * qid + (r >> 1) * 8;
            const float v0 = Watt[c * CMID + o] * LOG2E;
            const float v1 = Watt[(c + 1) * CMID + o] * LOG2E;
            pack_pair(v0, v1, Ahi[cc][r], Alo[cc][r]);
        }
    }
    __syncthreads();

    // static (buffer-relative) ldmatrix offsets
    uint32_t rowOff[8];
#pragma unroll
    for (int cc = 0; cc < 8; ++cc)
        rowOff[cc] = frow(16 * cc + (lane & 15)) + ((lane & 16) ? 16u : 0u);
    const uint32_t aggFOff = frow(16 * oc + (lane & 15)) + ((lane & 16) ? 16u : 0u);
    // phase-3 bases (agg rows alias via lane&7; D rows 8-15 ignored)
    const uint32_t aAgg0 = uS + OFF_AGG + (uint32_t)(lane & 7) * F_ROWSTRIDE
                         + ((lane & 16) ? 16u : 0u);
    const uint32_t aWg   = uS + OFF_WGH
                         + (uint32_t)(8 * warp + (lane & 7)) * F_ROWSTRIDE
                         + ((lane & 8) ? 16u : 0u);
    const int oP = 8 * warp + 2 * qid;            // phase 3: output channels
    const float bias0 = bglob[oP];
    const float bias1 = bglob[oP + 1];

    // ---- phase 1 builder (into F buffer `buf`) ----
    auto phase1 = [&](int gg, int buf) {
        char* sF = smem + buf * (2 * F_TILE);          // hi; lo at +F_TILE
        const int p0g = gg * 8;
        const int bbg = p0g >> 14;
        const int p   = p0g + pt1;
        const int n   = p & (NPTS - 1);
        const float* posB = pos + (size_t)bbg * NPTS * 3;
        const float cx = posB[n * 3 + 0];
        const float cy = posB[n * 3 + 1];
        const float cz = posB[n * 3 + 2];
        int myidx = 0;
        if (lane < 8) myidx = nidx[(size_t)p * KNN + kh * 8 + lane];
        const uint32_t rowbase = (uint32_t)(pt1 * 32 + kh * 16);

        // pass B: pre-split features, channel rows 64+lane, 96+lane
        {
            uint32_t gh[8], gl[8];
#pragma unroll
            for (int k2 = 0; k2 < 8; k2 += 2) {
                const int id0 = __shfl_sync(0xffffffffu, myidx, k2);
                const int id1 = __shfl_sync(0xffffffffu, myidx, k2 + 1);
                const uint32_t* x0 = g_xtp + ((size_t)bbg * NPTS + id0) * CIN;
                const uint32_t* x1 = g_xtp + ((size_t)bbg * NPTS + id1) * CIN;
                const uint32_t a0 = x0[lane],      a1 = x1[lane];
                const uint32_t b0 = x0[lane + 32], b1 = x1[lane + 32];
                gh[k2 >> 1]       = __byte_perm(a0, a1, 0x5410);
                gl[k2 >> 1]       = __byte_perm(a0, a1, 0x7632);
                gh[4 + (k2 >> 1)] = __byte_perm(b0, b1, 0x5410);
                gl[4 + (k2 >> 1)] = __byte_perm(b0, b1, 0x7632);
            }
            const uint32_t r0 = frow(64 + lane) + rowbase;
            const uint32_t r1 = frow(96 + lane) + rowbase;
            *(uint4*)(sF + r0)          = make_uint4(gh[0], gh[1], gh[2], gh[3]);
            *(uint4*)(sF + r0 + F_TILE) = make_uint4(gl[0], gl[1], gl[2], gl[3]);
            *(uint4*)(sF + r1)          = make_uint4(gh[4], gh[5], gh[6], gh[7]);
            *(uint4*)(sF + r1 + F_TILE) = make_uint4(gl[4], gl[5], gl[6], gl[7]);
        }
        // pass A: rel-MLP, channel rows lane, lane+32
        {
            uint32_t gh[8], gl[8];
#pragma unroll
            for (int k2 = 0; k2 < 8; k2 += 2) {
                float ra[2], rb[2];
#pragma unroll
                for (int s = 0; s < 2; ++s) {
                    const int id = __shfl_sync(0xffffffffu, myidx, k2 + s);
                    const float nx = posB[id * 3 + 0];
                    const float ny = posB[id * 3 + 1];
                    const float nz = posB[id * 3 + 2];
                    const float rx = nx - cx, ry = ny - cy, rz = nz - cz;
                    const float d  = sqrtf(rx * rx + ry * ry + rz * rz);
                    const float enc[10] = {cx, cy, cz, nx, ny, nz, rx, ry, rz, d};
                    float a0 = sbrel[lane];
                    float a1 = sbrel[lane + 32];
#pragma unroll
                    for (int e = 0; e < 10; ++e) {
                        a0 = fmaf(enc[e], sWrel[e * DREL + lane],      a0);
                        a1 = fmaf(enc[e], sWrel[e * DREL + lane + 32], a1);
                    }
                    ra[s] = fmaxf(a0, 0.0f);
                    rb[s] = fmaxf(a1, 0.0f);
                }
                pack_pair(ra[0], ra[1], gh[k2 >> 1],       gl[k2 >> 1]);
                pack_pair(rb[0], rb[1], gh[4 + (k2 >> 1)], gl[4 + (k2 >> 1)]);
            }
            const uint32_t r0 = frow(lane) + rowbase;
            const uint32_t r1 = frow(lane + 32) + rowbase;
            *(uint4*)(sF + r0)          = make_uint4(gh[0], gh[1], gh[2], gh[3]);
            *(uint4*)(sF + r0 + F_TILE) = make_uint4(gl[0], gl[1], gl[2], gl[3]);
            *(uint4*)(sF + r1)          = make_uint4(gh[4], gh[5], gh[6], gh[7]);
            *(uint4*)(sF + r1 + F_TILE) = make_uint4(gl[4], gl[5], gl[6], gl[7]);
        }
    };

    // ---- prologue: build first group into buffer 0 ----
    const int gstep = gridDim.x;
    const int g0 = blockIdx.x;
    int bcur = 0, par = 0;
    phase1(g0, 0);
    __syncthreads();

    for (int g = g0; g < GROUPS; g += gstep) {
        const int p0 = g * 8;
        const int bb = p0 >> 14;
        const int n0 = p0 & (NPTS - 1);
        const uint32_t uF = uS + (uint32_t)(bcur * (2 * F_TILE));
        const uint32_t aggBase = (uint32_t)(OFF_AGG + par * AGG_PAR);

        // ---- build NEXT group into the other buffer (no barrier needed) --
        const int gn = g + gstep;
        if (gn < GROUPS) phase1(gn, bcur ^ 1);

        // ================= phase 2: MMA scores + softmax + agg ============
        const uint32_t aggHiB = uF + aggFOff;
#pragma unroll 1
        for (int pp = 0; pp < 4; pp += 2) {
            const int ptX = pbase + pp;
            const int ptY = ptX + 1;
            const uint32_t colX = (uint32_t)ptX * 32;
            const uint32_t colY = colX + 32;
            float dAX[4] = {0.f, 0.f, 0.f, 0.f};
            float dBX[4] = {0.f, 0.f, 0.f, 0.f};
            float dAY[4] = {0.f, 0.f, 0.f, 0.f};
            float dBY[4] = {0.f, 0.f, 0.f, 0.f};
#pragma unroll
            for (int cc = 0; cc < 8; ++cc) {
                const uint32_t rB = uF + rowOff[cc];
                uint32_t bhX[4], blX[4], bhY[4], blY[4];
                LDSM_X4_T(bhX, rB + colX);
                LDSM_X4_T(bhY, rB + colY);
                LDSM_X4_T(blX, rB + colX + F_TILE);
                LDSM_X4_T(blY, rB + colY + F_TILE);
                MMA_BF16(dAX, Ahi[cc], bhX[0], bhX[1]);
                MMA_BF16(dBX, Ahi[cc], bhX[2], bhX[3]);
                MMA_BF16(dAY, Ahi[cc], bhY[0], bhY[1]);
                MMA_BF16(dBY, Ahi[cc], bhY[2], bhY[3]);
                MMA_BF16(dAX, Ahi[cc], blX[0], blX[1]);
                MMA_BF16(dBX, Ahi[cc], blX[2], blX[3]);
                MMA_BF16(dAY, Ahi[cc], blY[0], blY[1]);
                MMA_BF16(dBY, Ahi[cc], blY[2], blY[3]);
                MMA_BF16(dAX, Alo[cc], bhX[0], bhX[1]);
                MMA_BF16(dBX, Alo[cc], bhX[2], bhX[3]);
                MMA_BF16(dAY, Alo[cc], bhY[0], bhY[1]);
                MMA_BF16(dBY, Alo[cc], bhY[2], bhY[3]);
            }

#pragma unroll
            for (int s = 0; s < 2; ++s) {
                const int pt = s ? ptY : ptX;
                const uint32_t colb = s ? colY : colX;
                float* dA = s ? dAY : dAX;
                float* dB = s ? dBY : dBX;
                float vA[4] = {dA[0], dA[1], dB[0], dB[1]};
                float vB[4] = {dA[2], dA[3], dB[2], dB[3]};

                float mA = fmaxf(fmaxf(vA[0], vA[1]), fmaxf(vA[2], vA[3]));
                float mB = fmaxf(fmaxf(vB[0], vB[1]), fmaxf(vB[2], vB[3]));
                mA = fmaxf(mA, __shfl_xor_sync(0xffffffffu, mA, 1));
                mA = fmaxf(mA, __shfl_xor_sync(0xffffffffu, mA, 2));
                mB = fmaxf(mB, __shfl_xor_sync(0xffffffffu, mB, 1));
                mB = fmaxf(mB, __shfl_xor_sync(0xffffffffu, mB, 2));

                float sA = 0.f, sB = 0.f;
#pragma unroll
                for (int j = 0; j < 4; ++j) {
                    vA[j] = fast_exp2(vA[j] - mA); sA += vA[j];
                    vB[j] = fast_exp2(vB[j] - mB); sB += vB[j];
                }
                sA += __shfl_xor_sync(0xffffffffu, sA, 1);
                sA += __shfl_xor_sync(0xffffffffu, sA, 2);
                sB += __shfl_xor_sync(0xffffffffu, sB, 1);
                sB += __shfl_xor_sync(0xffffffffu, sB, 2);

                uint32_t fh[4], fl[4];
                LDSM_X4(fh, aggHiB + colb);
                LDSM_X4(fl, aggHiB + F_TILE + colb);

                float aggA, aggB;
                {
                    float2 h, l, f0, f1;
                    h = __bfloat1622float2(*(__nv_bfloat162*)&fh[0]);
                    l = __bfloat1622float2(*(__nv_bfloat162*)&fl[0]);
                    f0.x = h.x + l.x; f0.y = h.y + l.y;
                    h = __bfloat1622float2(*(__nv_bfloat162*)&fh[2]);
                    l = __bfloat1622float2(*(__nv_bfloat162*)&fl[2]);
                    f1.x = h.x + l.x; f1.y = h.y + l.y;
                    aggA = vA[0] * f0.x + vA[1] * f0.y + vA[2] * f1.x + vA[3] * f1.y;

                    h = __bfloat1622float2(*(__nv_bfloat162*)&fh[1]);
                    l = __bfloat1622float2(*(__nv_bfloat162*)&fl[1]);
                    f0.x = h.x + l.x; f0.y = h.y + l.y;
                    h = __bfloat1622float2(*(__nv_bfloat162*)&fh[3]);
                    l = __bfloat1622float2(*(__nv_bfloat162*)&fl[3]);
                    f1.x = h.x + l.x; f1.y = h.y + l.y;
                    aggB = vB[0] * f0.x + vB[1] * f0.y + vB[2] * f1.x + vB[3] * f1.y;
                }
                aggA += __shfl_xor_sync(0xffffffffu, aggA, 1);
                aggA += __shfl_xor_sync(0xffffffffu, aggA, 2);
                aggB += __shfl_xor_sync(0xffffffffu, aggB, 1);
                aggB += __shfl_xor_sync(0xffffffffu, aggB, 2);

                if (qid == 0) {
                    const float wA = aggA / sA;
                    const float wB = aggB / sB;
                    const uint32_t rb2 = aggBase + (uint32_t)pt * F_ROWSTRIDE;
                    const uint32_t c0b = (uint32_t)(16 * oc + gid) * 2;
                    const __nv_bfloat16 hA = __float2bfloat16(wA);
                    const __nv_bfloat16 lA = __float2bfloat16(wA - __bfloat162float(hA));
                    const __nv_bfloat16 hB = __float2bfloat16(wB);
                    const __nv_bfloat16 lB = __float2bfloat16(wB - __bfloat162float(hB));
                    *(uint16_t*)(smem + rb2 + c0b)                  = *(const uint16_t*)&hA;
                    *(uint16_t*)(smem + rb2 + AGG_TILE + c0b)       = *(const uint16_t*)&lA;
                    *(uint16_t*)(smem + rb2 + c0b + 16)             = *(const uint16_t*)&hB;
                    *(uint16_t*)(smem + rb2 + AGG_TILE + c0b + 16)  = *(const uint16_t*)&lB;
                }
            }
        }
        __syncthreads();   // ONE barrier: agg complete + next F complete

        // ================= phase 3: out-GEMM on tensor cores ==============
        {
            const uint32_t aA = aAgg0 + (uint32_t)(par * AGG_PAR);
            float dP[4] = {0.f, 0.f, 0.f, 0.f};
            float dQ[4] = {0.f, 0.f, 0.f, 0.f};
#pragma unroll
            for (int cc = 0; cc < 8; ++cc) {
                uint32_t ah[4], al[4], bh0, bh1, bl0, bl1;
                LDSM_X4(ah, aA + cc * 32);
                LDSM_X4(al, aA + AGG_TILE + cc * 32);
                LDSM_X2(bh0, bh1, aWg + cc * 32);
                LDSM_X2(bl0, bl1, aWg + F_TILE + cc * 32);
                MMA_BF16(dP, ah, bh0, bh1);
                MMA_BF16(dQ, ah, bl0, bl1);
                MMA_BF16(dQ, al, bh0, bh1);
            }
            const float r0 = fmaxf(dP[0] + dQ[0] + bias0, 0.0f);
            const float r1 = fmaxf(dP[1] + dQ[1] + bias1, 0.0f);
            float* ob = out + (size_t)bb * COUT * NPTS + n0 + gid;
            ob[(size_t)oP * NPTS]       = r0;
            ob[(size_t)(oP + 1) * NPTS] = r1;
        }
        bcur ^= 1;
        par  ^= 1;
    }
}

// ---------------------------------------------------------------------------
extern "C" void kernel_launch(void* const* d_in, const int* in_sizes, int n_in,
                              void* d_out, int out_size) {
    const float* x     = (const float*)d_in[0];
    const float* pos   = (const float*)d_in[1];
    const int*   nidx  = (const int*)  d_in[2];
    const float* Wrel  = (const float*)d_in[3];
    const float* brel  = (const float*)d_in[4];
    const float* Watt  = (const float*)d_in[5];
    const float* Wglob = (const float*)d_in[6];
    const float* bglob = (const float*)d_in[7];
    float*       out   = (float*)d_out;

    transpose_x_kernel<<<dim3(NPTS / 32, CIN / 32, BATCH), dim3(32, 8)>>>(x);

    cudaFuncSetAttribute(randlanet_mma_kernel,
                         cudaFuncAttributeMaxDynamicSharedMemorySize, SMEM_BYTES);
    randlanet_mma_kernel<<<148, NTHREADS, SMEM_BYTES>>>(pos, nidx, Wrel, brel,
                                                        Watt, Wglob, bglob, out);
}